// round 11
// baseline (speedup 1.0000x reference)
#include <cuda_runtime.h>

#define N_NODES 50000
#define IN_F    128
#define OUT_F   64
#define HEADS   2
#define ALPHA   0.2f

__device__ float  g_v[512];          // [which(i/j)][head][128]
__device__ float2 g_si[N_NODES];
__device__ float2 g_sj[N_NODES];
__device__ float2 g_c[N_NODES];      // per-node sum of exp(e) per head
__device__ float  g_Z[2];            // global softmax denominator per head

// ---------------------------------------------------------------------------
// 1) v = W @ a (both halves, both heads); also zero g_Z
__global__ void prep_v_kernel(const float* __restrict__ W,
                              const float* __restrict__ a) {
    int t = threadIdx.x;            // 512 threads
    if (t < 2) g_Z[t] = 0.0f;
    int which = t >> 8;
    int h     = (t >> 7) & 1;
    int i     = t & 127;
    const float* wrow = W + h * (IN_F * OUT_F) + i * OUT_F;
    const float* av   = a + h * (2 * OUT_F) + which * OUT_F;
    float s = 0.f;
#pragma unroll 16
    for (int o = 0; o < OUT_F; o++) s += wrow[o] * av[o];
    g_v[which * 256 + h * 128 + i] = s;
}

// ---------------------------------------------------------------------------
// 2) per-node scores (one warp per node); also zeroes g_c
__global__ void __launch_bounds__(256) node_s_kernel(const float* __restrict__ x, int N) {
    __shared__ float vsm[512];
    int tid = threadIdx.x;
    vsm[tid]       = g_v[tid];
    vsm[tid + 256] = g_v[tid + 256];
    __syncthreads();

    int warp = tid >> 5, lane = tid & 31;
    int n = blockIdx.x * 8 + warp;
    if (n >= N) return;

    float4 xv = ((const float4*)x)[(size_t)n * 32 + lane];
    const float4* v4 = (const float4*)vsm;
    float4 vi0 = v4[lane];
    float4 vi1 = v4[32 + lane];
    float4 vj0 = v4[64 + lane];
    float4 vj1 = v4[96 + lane];

    float si0 = xv.x*vi0.x + xv.y*vi0.y + xv.z*vi0.z + xv.w*vi0.w;
    float si1 = xv.x*vi1.x + xv.y*vi1.y + xv.z*vi1.z + xv.w*vi1.w;
    float sj0 = xv.x*vj0.x + xv.y*vj0.y + xv.z*vj0.z + xv.w*vj0.w;
    float sj1 = xv.x*vj1.x + xv.y*vj1.y + xv.z*vj1.z + xv.w*vj1.w;

#pragma unroll
    for (int off = 16; off; off >>= 1) {
        si0 += __shfl_xor_sync(0xffffffffu, si0, off);
        si1 += __shfl_xor_sync(0xffffffffu, si1, off);
        sj0 += __shfl_xor_sync(0xffffffffu, sj0, off);
        sj1 += __shfl_xor_sync(0xffffffffu, sj1, off);
    }
    if (lane == 0) {
        g_si[n] = make_float2(si0, si1);
        g_sj[n] = make_float2(sj0, sj1);
        g_c[n]  = make_float2(0.f, 0.f);
    }
}

// ---------------------------------------------------------------------------
// 3) edge pass + fused global-Z reduction (frozen: measured)
__global__ void __launch_bounds__(256) edge_kernel(const int* __restrict__ ei, int E) {
    int k = blockIdx.x * blockDim.x + threadIdx.x;
    float z0 = 0.f, z1 = 0.f;
    if (k < E) {
        int src = __ldg(ei + k);
        int dst = __ldg(ei + E + k);
        float2 si = g_si[src];
        float2 sj = g_sj[dst];
        float e0 = si.x + sj.x;
        float e1 = si.y + sj.y;
        e0 = e0 > 0.f ? e0 : ALPHA * e0;
        e1 = e1 > 0.f ? e1 : ALPHA * e1;
        z0 = __expf(e0);
        z1 = __expf(e1);
        asm volatile("red.global.add.v2.f32 [%0], {%1, %2};"
                     :: "l"(&g_c[dst]), "f"(z0), "f"(z1) : "memory");
    }
#pragma unroll
    for (int off = 16; off; off >>= 1) {
        z0 += __shfl_xor_sync(0xffffffffu, z0, off);
        z1 += __shfl_xor_sync(0xffffffffu, z1, off);
    }
    __shared__ float s0[8], s1[8];
    int warp = threadIdx.x >> 5, lane = threadIdx.x & 31;
    if (lane == 0) { s0[warp] = z0; s1[warp] = z1; }
    __syncthreads();
    if (threadIdx.x == 0) {
        float t0 = 0.f, t1 = 0.f;
#pragma unroll
        for (int w = 0; w < 8; w++) { t0 += s0[w]; t1 += s1[w]; }
        asm volatile("red.global.add.v2.f32 [%0], {%1, %2};"
                     :: "l"(g_Z), "f"(t0), "f"(t1) : "memory");
    }
}

// ---------------------------------------------------------------------------
// 4) out = (x @ W) * c/Z -- tf32 mma.sync, persistent, FRAGMENT-PACKED smem.
//    TILE_M=64, smem = asf 32KB + bsf 64KB = 96KB -> 2 CTAs/SM (16 warps).
//    asf: per (m-band, kstep, lane) a 16B chunk = the lane's exact A fragment
//         (tf32 converted at staging) -> ONE LDS.128, conflict-free (dense
//         16B/lane = 4 clean 128B phases).
//    bsf: 4 planes j=0..3; plane j holds per (wn, kstep, lane) a 16B chunk
//         = B fragments for ni=2j,2j+1 -> 4x LDS.128/k-step, conflict-free.
//    Mainloop/warp/k-step: 5 LDS.128 + 8 HMMA (was 24 LDS.32 + 8 CVT + 16 HMMA).
#define TILE_M 64

__device__ __forceinline__ unsigned f2tf32(float f) {
    unsigned u;
    asm("cvt.rna.tf32.f32 %0, %1;" : "=r"(u) : "f"(f));
    return u;
}

__device__ __forceinline__ void mma_tf32(float* d,
                                         unsigned a0, unsigned a1, unsigned a2, unsigned a3,
                                         unsigned b0, unsigned b1) {
    asm volatile("mma.sync.aligned.m16n8k8.row.col.f32.tf32.tf32.f32 "
                 "{%0,%1,%2,%3}, {%4,%5,%6,%7}, {%8,%9}, {%0,%1,%2,%3};"
                 : "+f"(d[0]), "+f"(d[1]), "+f"(d[2]), "+f"(d[3])
                 : "r"(a0), "r"(a1), "r"(a2), "r"(a3), "r"(b0), "r"(b1));
}

__global__ void __launch_bounds__(256, 2) out_gemm_kernel(const float* __restrict__ x,
                                                          const float* __restrict__ W,
                                                          float* __restrict__ out,
                                                          int N, int numTiles) {
    extern __shared__ unsigned smem[];
    unsigned* asf = smem;           // [4 mband][16 ks][32 lane][4]  = 8192 words
    unsigned* bsf = smem + 8192;    // [4 j][2 wn][16 ks][32 lane][4] = 16384 words

    int tid = threadIdx.x;

    // stage W once into fragment-packed planes:
    // idx -> w4 | lane | ks | wn | j ;  ni = 2j + (w4>>1), sel = w4&1
    for (int idx = tid; idx < 16384; idx += 256) {
        int w4   = idx & 3;
        int lane = (idx >> 2) & 31;
        int ks   = (idx >> 7) & 15;
        int wn   = (idx >> 11) & 1;
        int j    = (idx >> 12) & 3;
        int g = lane >> 2, t = lane & 3;
        int ni  = 2 * j + (w4 >> 1);
        int sel = w4 & 1;
        int c = wn * 64 + ni * 8 + g;          // output column (h*64+o)
        int k = ks * 8 + t + sel * 4;          // K index
        bsf[idx] = f2tf32(W[((size_t)(c >> 6) * 128 + k) * 64 + (c & 63)]);
    }

    int wid  = tid >> 5, lane = tid & 31;
    int wm   = wid >> 1;            // 0..3 : 16-row band
    int wn   = wid & 1;             // 0..1 : 64-col band (== head)
    int g    = lane >> 2;
    int t    = lane & 3;
    float rz = 1.0f / g_Z[wn];

    const float4* x4 = (const float4*)x;

    for (int tile = blockIdx.x; tile < numTiles; tile += gridDim.x) {
        int n0 = tile * TILE_M;
        __syncthreads();    // previous iteration's asf readers done

        // stage x tile into fragment-packed asf (tf32 at staging)
        for (int idx = tid; idx < TILE_M * 32; idx += 256) {
            int r  = idx >> 5;
            int c4 = idx & 31;
            int n  = n0 + r;
            float4 v = make_float4(0.f, 0.f, 0.f, 0.f);
            if (n < N) v = x4[(size_t)n * 32 + c4];
            unsigned q[4] = {f2tf32(v.x), f2tf32(v.y), f2tf32(v.z), f2tf32(v.w)};
            int mb = r >> 4, rr = r & 15;
            int hi = rr >> 3, gg = rr & 7;
            int ks = c4 >> 1;            // k = 4*c4+m, m<4 -> same ks
            int cs = c4 & 1;             // 0: cols t, 1: cols t+4
#pragma unroll
            for (int m = 0; m < 4; m++) {
                int ln = gg * 4 + m;     // t_lo = m
                asf[(((mb * 16 + ks) * 32) + ln) * 4 + hi + 2 * cs] = q[m];
            }
        }
        __syncthreads();

        float acc[8][4];
#pragma unroll
        for (int ni = 0; ni < 8; ni++)
#pragma unroll
            for (int q = 0; q < 4; q++) acc[ni][q] = 0.f;

        const uint4* aP  = (const uint4*)(asf + (wm * 16) * 128) + lane;
        const uint4* bP0 = (const uint4*)(bsf + (wn * 16) * 128) + lane;       // j=0
#pragma unroll
        for (int ks = 0; ks < 16; ks++) {
            uint4 a4 = aP[ks * 32];
#pragma unroll
            for (int j = 0; j < 4; j++) {
                uint4 b4 = bP0[j * 1024 + ks * 32];   // j plane stride = 4096 words
                mma_tf32(acc[2 * j],     a4.x, a4.y, a4.z, a4.w, b4.x, b4.y);
                mma_tf32(acc[2 * j + 1], a4.x, a4.y, a4.z, a4.w, b4.z, b4.w);
            }
        }

        // epilogue: scale by c[n,head]/Z_head; head == wn
        int r0 = n0 + wm * 16 + g;   // rows for c0,c1
        int r1 = r0 + 8;             // rows for c2,c3
        float scl0 = 0.f, scl1 = 0.f;
        if (r0 < N) {
            float2 cc = g_c[r0];
            scl0 = (wn ? cc.y : cc.x) * rz;
        }
        if (r1 < N) {
            float2 cc = g_c[r1];
            scl1 = (wn ? cc.y : cc.x) * rz;
        }
#pragma unroll
        for (int ni = 0; ni < 8; ni++) {
            int col = wn * 64 + ni * 8 + 2 * t;
            if (r0 < N)
                *(float2*)&out[(size_t)r0 * 128 + col] =
                    make_float2(acc[ni][0] * scl0, acc[ni][1] * scl0);
            if (r1 < N)
                *(float2*)&out[(size_t)r1 * 128 + col] =
                    make_float2(acc[ni][2] * scl1, acc[ni][3] * scl1);
        }
    }
}

// ---------------------------------------------------------------------------
extern "C" void kernel_launch(void* const* d_in, const int* in_sizes, int n_in,
                              void* d_out, int out_size) {
    const float* x  = (const float*)d_in[0];
    const float* W  = (const float*)d_in[1];
    const float* a  = (const float*)d_in[2];
    const int*   ei = (const int*)d_in[3];
    float* out = (float*)d_out;

    int N = in_sizes[0] / IN_F;
    if (N > N_NODES) N = N_NODES;
    int E = in_sizes[3] / 2;
    int numTiles = (N + TILE_M - 1) / TILE_M;

    prep_v_kernel<<<1, 512>>>(W, a);
    node_s_kernel<<<(N + 7) / 8, 256>>>(x, N);
    edge_kernel<<<(E + 255) / 256, 256>>>(ei, E);

    const int smem_bytes = (8192 + 16384) * 4;   // 96 KB -> 2 CTAs/SM
    cudaFuncSetAttribute(out_gemm_kernel,
                         cudaFuncAttributeMaxDynamicSharedMemorySize, smem_bytes);
    int grid = numTiles < 296 ? numTiles : 296;
    out_gemm_kernel<<<grid, 256, smem_bytes>>>(x, W, out, N, numTiles);
}

// round 12
// speedup vs baseline: 1.1961x; 1.1961x over previous
#include <cuda_runtime.h>

#define N_NODES 50000
#define IN_F    128
#define OUT_F   64
#define HEADS   2
#define ALPHA   0.2f

__device__ float  g_v[512];          // [which(i/j)][head][128]
__device__ float2 g_si[N_NODES];
__device__ float2 g_sj[N_NODES];
__device__ float2 g_c[N_NODES];      // per-node sum of exp(e) per head
__device__ float  g_Z[2];            // global softmax denominator per head
__device__ unsigned g_wpack[16384];  // W in tf32 MMA-fragment order (64KB)

// ---------------------------------------------------------------------------
// 1) v = W @ a (both halves, both heads); also zero g_Z
__global__ void prep_v_kernel(const float* __restrict__ W,
                              const float* __restrict__ a) {
    int t = threadIdx.x;            // 512 threads
    if (t < 2) g_Z[t] = 0.0f;
    int which = t >> 8;
    int h     = (t >> 7) & 1;
    int i     = t & 127;
    const float* wrow = W + h * (IN_F * OUT_F) + i * OUT_F;
    const float* av   = a + h * (2 * OUT_F) + which * OUT_F;
    float s = 0.f;
#pragma unroll 16
    for (int o = 0; o < OUT_F; o++) s += wrow[o] * av[o];
    g_v[which * 256 + h * 128 + i] = s;
}

// ---------------------------------------------------------------------------
__device__ __forceinline__ unsigned f2tf32(float f) {
    unsigned u;
    asm("cvt.rna.tf32.f32 %0, %1;" : "=r"(u) : "f"(f));
    return u;
}

// 1b) pack W into per-warp MMA fragment order:
//     g_wpack[((w*16+ks)*32+lane)*4 + q]; warp w owns cols [w*16, w*16+16)
//     q = ni_local*2 + sel : b_sel for col w*16+ni_local*8+g, k = ks*8+t+sel*4
__global__ void prep_w_kernel(const float* __restrict__ W) {
    int idx = blockIdx.x * 256 + threadIdx.x;      // 0..16383
    int q    = idx & 3;
    int lane = (idx >> 2) & 31;
    int ks   = (idx >> 7) & 15;
    int w    = (idx >> 11) & 7;
    int g = lane >> 2, t = lane & 3;
    int ni  = q >> 1;
    int sel = q & 1;
    int c = w * 16 + ni * 8 + g;          // output column (h*64+o)
    int k = ks * 8 + t + sel * 4;
    int h = c >> 6, o = c & 63;
    g_wpack[idx] = f2tf32(W[((size_t)h * 128 + k) * 64 + o]);
}

// ---------------------------------------------------------------------------
// 2) per-node scores (one warp per node); also zeroes g_c
__global__ void __launch_bounds__(256) node_s_kernel(const float* __restrict__ x, int N) {
    __shared__ float vsm[512];
    int tid = threadIdx.x;
    vsm[tid]       = g_v[tid];
    vsm[tid + 256] = g_v[tid + 256];
    __syncthreads();

    int warp = tid >> 5, lane = tid & 31;
    int n = blockIdx.x * 8 + warp;
    if (n >= N) return;

    float4 xv = ((const float4*)x)[(size_t)n * 32 + lane];
    const float4* v4 = (const float4*)vsm;
    float4 vi0 = v4[lane];
    float4 vi1 = v4[32 + lane];
    float4 vj0 = v4[64 + lane];
    float4 vj1 = v4[96 + lane];

    float si0 = xv.x*vi0.x + xv.y*vi0.y + xv.z*vi0.z + xv.w*vi0.w;
    float si1 = xv.x*vi1.x + xv.y*vi1.y + xv.z*vi1.z + xv.w*vi1.w;
    float sj0 = xv.x*vj0.x + xv.y*vj0.y + xv.z*vj0.z + xv.w*vj0.w;
    float sj1 = xv.x*vj1.x + xv.y*vj1.y + xv.z*vj1.z + xv.w*vj1.w;

#pragma unroll
    for (int off = 16; off; off >>= 1) {
        si0 += __shfl_xor_sync(0xffffffffu, si0, off);
        si1 += __shfl_xor_sync(0xffffffffu, si1, off);
        sj0 += __shfl_xor_sync(0xffffffffu, sj0, off);
        sj1 += __shfl_xor_sync(0xffffffffu, sj1, off);
    }
    if (lane == 0) {
        g_si[n] = make_float2(si0, si1);
        g_sj[n] = make_float2(sj0, sj1);
        g_c[n]  = make_float2(0.f, 0.f);
    }
}

// ---------------------------------------------------------------------------
// 3) edge pass + fused global-Z reduction (frozen: measured)
__global__ void __launch_bounds__(256) edge_kernel(const int* __restrict__ ei, int E) {
    int k = blockIdx.x * blockDim.x + threadIdx.x;
    float z0 = 0.f, z1 = 0.f;
    if (k < E) {
        int src = __ldg(ei + k);
        int dst = __ldg(ei + E + k);
        float2 si = g_si[src];
        float2 sj = g_sj[dst];
        float e0 = si.x + sj.x;
        float e1 = si.y + sj.y;
        e0 = e0 > 0.f ? e0 : ALPHA * e0;
        e1 = e1 > 0.f ? e1 : ALPHA * e1;
        z0 = __expf(e0);
        z1 = __expf(e1);
        asm volatile("red.global.add.v2.f32 [%0], {%1, %2};"
                     :: "l"(&g_c[dst]), "f"(z0), "f"(z1) : "memory");
    }
#pragma unroll
    for (int off = 16; off; off >>= 1) {
        z0 += __shfl_xor_sync(0xffffffffu, z0, off);
        z1 += __shfl_xor_sync(0xffffffffu, z1, off);
    }
    __shared__ float s0[8], s1[8];
    int warp = threadIdx.x >> 5, lane = threadIdx.x & 31;
    if (lane == 0) { s0[warp] = z0; s1[warp] = z1; }
    __syncthreads();
    if (threadIdx.x == 0) {
        float t0 = 0.f, t1 = 0.f;
#pragma unroll
        for (int w = 0; w < 8; w++) { t0 += s0[w]; t1 += s1[w]; }
        asm volatile("red.global.add.v2.f32 [%0], {%1, %2};"
                     :: "l"(g_Z), "f"(t0), "f"(t1) : "memory");
    }
}

// ---------------------------------------------------------------------------
// 4) out = (x @ W) * c/Z -- tf32 mma.sync, persistent, B IN REGISTERS.
//    TILE_M=64, 256 threads = 8 warps; each warp covers ALL 64 rows
//    (4 m-frags) x a 16-col band (2 ni). B fragments live in registers
//    (loaded per K-half from g_wpack via LDG.128, L1-resident) -> ZERO B
//    smem traffic. A: R7-proven xs[r][132] layout, conflict-free LDS.32.
//    smem 34KB, ~95 regs -> 2 CTAs/SM, 4 warps/SMSP.
#define XS_STRIDE 132
#define TILE_M    64

__device__ __forceinline__ void mma_tf32(float* d,
                                         unsigned a0, unsigned a1, unsigned a2, unsigned a3,
                                         unsigned b0, unsigned b1) {
    asm volatile("mma.sync.aligned.m16n8k8.row.col.f32.tf32.tf32.f32 "
                 "{%0,%1,%2,%3}, {%4,%5,%6,%7}, {%8,%9}, {%0,%1,%2,%3};"
                 : "+f"(d[0]), "+f"(d[1]), "+f"(d[2]), "+f"(d[3])
                 : "r"(a0), "r"(a1), "r"(a2), "r"(a3), "r"(b0), "r"(b1));
}

__global__ void __launch_bounds__(256, 2) out_gemm_kernel(const float* __restrict__ x,
                                                          float* __restrict__ out,
                                                          int N, int numTiles) {
    __shared__ unsigned xs[TILE_M * XS_STRIDE];   // f32-as-bits x tile

    int tid = threadIdx.x;
    int wn   = tid >> 5;            // warp 0..7 : 16-col band
    int lane = tid & 31;
    int g    = lane >> 2;
    int t    = lane & 3;
    int head = wn >> 2;             // cols [wn*16, wn*16+16) all in one head
    float rz = 1.0f / g_Z[head];

    const float4* x4 = (const float4*)x;

    for (int tile = blockIdx.x; tile < numTiles; tile += gridDim.x) {
        int n0 = tile * TILE_M;
        __syncthreads();    // previous iteration's xs readers done

        // stage x tile: 64 rows x 32 float4 / 256 thr = 8 LDG.128+STS.128 each
#pragma unroll
        for (int it = 0; it < 8; it++) {
            int idx = tid + it * 256;
            int r   = idx >> 5;
            int k4  = idx & 31;
            int n   = n0 + r;
            float4 v = make_float4(0.f, 0.f, 0.f, 0.f);
            if (n < N) v = x4[(size_t)n * 32 + k4];
            *(uint4*)&xs[r * XS_STRIDE + k4 * 4] =
                make_uint4(__float_as_uint(v.x), __float_as_uint(v.y),
                           __float_as_uint(v.z), __float_as_uint(v.w));
        }
        __syncthreads();

        float acc[4][2][4];
#pragma unroll
        for (int mi = 0; mi < 4; mi++)
#pragma unroll
            for (int ni = 0; ni < 2; ni++)
#pragma unroll
                for (int q = 0; q < 4; q++) acc[mi][ni][q] = 0.f;

#pragma unroll
        for (int half = 0; half < 2; half++) {
            // load this half's B fragments into registers (L1-warm)
            uint4 bh[8];
            const uint4* wp = (const uint4*)g_wpack + (wn * 16 + half * 8) * 32 + lane;
#pragma unroll
            for (int k2 = 0; k2 < 8; k2++) bh[k2] = wp[k2 * 32];

#pragma unroll
            for (int k2 = 0; k2 < 8; k2++) {
                int k0 = (half * 8 + k2) * 8;
                unsigned av[4][4];
#pragma unroll
                for (int mi = 0; mi < 4; mi++) {
                    int r0 = mi * 16;
                    av[mi][0] = f2tf32(__uint_as_float(xs[(r0 + g)     * XS_STRIDE + k0 + t]));
                    av[mi][1] = f2tf32(__uint_as_float(xs[(r0 + g + 8) * XS_STRIDE + k0 + t]));
                    av[mi][2] = f2tf32(__uint_as_float(xs[(r0 + g)     * XS_STRIDE + k0 + t + 4]));
                    av[mi][3] = f2tf32(__uint_as_float(xs[(r0 + g + 8) * XS_STRIDE + k0 + t + 4]));
                }
#pragma unroll
                for (int mi = 0; mi < 4; mi++) {
                    mma_tf32(acc[mi][0], av[mi][0], av[mi][1], av[mi][2], av[mi][3],
                             bh[k2].x, bh[k2].y);
                    mma_tf32(acc[mi][1], av[mi][0], av[mi][1], av[mi][2], av[mi][3],
                             bh[k2].z, bh[k2].w);
                }
            }
        }

        // epilogue: scale by c[n,head]/Z_head
#pragma unroll
        for (int mi = 0; mi < 4; mi++) {
            int r0 = n0 + mi * 16 + g;   // rows for c0,c1
            int r1 = r0 + 8;             // rows for c2,c3
            float scl0 = 0.f, scl1 = 0.f;
            if (r0 < N) {
                float2 cc = g_c[r0];
                scl0 = (head ? cc.y : cc.x) * rz;
            }
            if (r1 < N) {
                float2 cc = g_c[r1];
                scl1 = (head ? cc.y : cc.x) * rz;
            }
#pragma unroll
            for (int ni = 0; ni < 2; ni++) {
                int col = wn * 16 + ni * 8 + 2 * t;
                if (r0 < N)
                    *(float2*)&out[(size_t)r0 * 128 + col] =
                        make_float2(acc[mi][ni][0] * scl0, acc[mi][ni][1] * scl0);
                if (r1 < N)
                    *(float2*)&out[(size_t)r1 * 128 + col] =
                        make_float2(acc[mi][ni][2] * scl1, acc[mi][ni][3] * scl1);
            }
        }
    }
}

// ---------------------------------------------------------------------------
extern "C" void kernel_launch(void* const* d_in, const int* in_sizes, int n_in,
                              void* d_out, int out_size) {
    const float* x  = (const float*)d_in[0];
    const float* W  = (const float*)d_in[1];
    const float* a  = (const float*)d_in[2];
    const int*   ei = (const int*)d_in[3];
    float* out = (float*)d_out;

    int N = in_sizes[0] / IN_F;
    if (N > N_NODES) N = N_NODES;
    int E = in_sizes[3] / 2;
    int numTiles = (N + TILE_M - 1) / TILE_M;

    prep_v_kernel<<<1, 512>>>(W, a);
    prep_w_kernel<<<64, 256>>>(W);
    node_s_kernel<<<(N + 7) / 8, 256>>>(x, N);
    edge_kernel<<<(E + 255) / 256, 256>>>(ei, E);

    int grid = numTiles < 296 ? numTiles : 296;
    out_gemm_kernel<<<grid, 256>>>(x, out, N, numTiles);
}

// round 14
// speedup vs baseline: 1.3852x; 1.1581x over previous
#include <cuda_runtime.h>

#define N_NODES 50000
#define IN_F    128
#define OUT_F   64
#define HEADS   2
#define ALPHA   0.2f

__device__ float  g_v[512];          // [which(i/j)][head][128]
__device__ float2 g_si[N_NODES];
__device__ float2 g_sj[N_NODES];
__device__ float2 g_c[N_NODES];      // per-node sum of exp(e) per head
__device__ float  g_Z[2];            // global softmax denominator per head
__device__ unsigned g_wpack[16384];  // W in tf32 MMA-fragment order (64KB)

__device__ __forceinline__ unsigned f2tf32(float f) {
    unsigned u;
    asm("cvt.rna.tf32.f32 %0, %1;" : "=r"(u) : "f"(f));
    return u;
}

// ---------------------------------------------------------------------------
// 1) merged prep: W fragment pack (all 64 blocks) + v = W@a + zero Z
//    (blocks 0-1 cover the 512 v entries)
__global__ void prep_kernel(const float* __restrict__ W,
                            const float* __restrict__ a) {
    int idx = blockIdx.x * 256 + threadIdx.x;      // 0..16383

    // --- wpack: g_wpack[((w*16+ks)*32+lane)*4 + q], warp w owns cols [w*16,w*16+16)
    {
        int q    = idx & 3;
        int lane = (idx >> 2) & 31;
        int ks   = (idx >> 7) & 15;
        int w    = (idx >> 11) & 7;
        int g = lane >> 2, t = lane & 3;
        int ni  = q >> 1;
        int sel = q & 1;
        int c = w * 16 + ni * 8 + g;          // output column (h*64+o)
        int k = ks * 8 + t + sel * 4;
        int h = c >> 6, o = c & 63;
        g_wpack[idx] = f2tf32(W[((size_t)h * 128 + k) * 64 + o]);
    }

    // --- v + Z
    if (idx < 2) g_Z[idx] = 0.0f;
    if (idx < 512) {
        int which = idx >> 8;
        int h     = (idx >> 7) & 1;
        int i     = idx & 127;
        const float* wrow = W + h * (IN_F * OUT_F) + i * OUT_F;
        const float* av   = a + h * (2 * OUT_F) + which * OUT_F;
        float s = 0.f;
#pragma unroll 16
        for (int o = 0; o < OUT_F; o++) s += wrow[o] * av[o];
        g_v[which * 256 + h * 128 + i] = s;
    }
}

// ---------------------------------------------------------------------------
// 2) per-node scores (one warp per node); also zeroes g_c  (frozen)
__global__ void __launch_bounds__(256) node_s_kernel(const float* __restrict__ x, int N) {
    __shared__ float vsm[512];
    int tid = threadIdx.x;
    vsm[tid]       = g_v[tid];
    vsm[tid + 256] = g_v[tid + 256];
    __syncthreads();

    int warp = tid >> 5, lane = tid & 31;
    int n = blockIdx.x * 8 + warp;
    if (n >= N) return;

    float4 xv = ((const float4*)x)[(size_t)n * 32 + lane];
    const float4* v4 = (const float4*)vsm;
    float4 vi0 = v4[lane];
    float4 vi1 = v4[32 + lane];
    float4 vj0 = v4[64 + lane];
    float4 vj1 = v4[96 + lane];

    float si0 = xv.x*vi0.x + xv.y*vi0.y + xv.z*vi0.z + xv.w*vi0.w;
    float si1 = xv.x*vi1.x + xv.y*vi1.y + xv.z*vi1.z + xv.w*vi1.w;
    float sj0 = xv.x*vj0.x + xv.y*vj0.y + xv.z*vj0.z + xv.w*vj0.w;
    float sj1 = xv.x*vj1.x + xv.y*vj1.y + xv.z*vj1.z + xv.w*vj1.w;

#pragma unroll
    for (int off = 16; off; off >>= 1) {
        si0 += __shfl_xor_sync(0xffffffffu, si0, off);
        si1 += __shfl_xor_sync(0xffffffffu, si1, off);
        sj0 += __shfl_xor_sync(0xffffffffu, sj0, off);
        sj1 += __shfl_xor_sync(0xffffffffu, sj1, off);
    }
    if (lane == 0) {
        g_si[n] = make_float2(si0, si1);
        g_sj[n] = make_float2(sj0, sj1);
        g_c[n]  = make_float2(0.f, 0.f);
    }
}

// ---------------------------------------------------------------------------
// 3) edge pass: 4 edges/thread, ALL gathers issued before any consumption
//    (MLP=8 per thread hides L2 latency); one red.add.v2 per edge; fused
//    global-Z block reduction.
__device__ __forceinline__ float2 edge_w(float2 si, float2 sj) {
    float e0 = si.x + sj.x;
    float e1 = si.y + sj.y;
    e0 = e0 > 0.f ? e0 : ALPHA * e0;
    e1 = e1 > 0.f ? e1 : ALPHA * e1;
    return make_float2(__expf(e0), __expf(e1));
}

__global__ void __launch_bounds__(256) edge_kernel(const int* __restrict__ ei, int E) {
    int k = (blockIdx.x * blockDim.x + threadIdx.x) * 4;
    float z0 = 0.f, z1 = 0.f;
    if (k + 3 < E) {
        int4 s4 = *(const int4*)(ei + k);
        int4 d4 = *(const int4*)(ei + E + k);
        float2 si0 = __ldg(&g_si[s4.x]);
        float2 si1 = __ldg(&g_si[s4.y]);
        float2 si2 = __ldg(&g_si[s4.z]);
        float2 si3 = __ldg(&g_si[s4.w]);
        float2 sj0 = __ldg(&g_sj[d4.x]);
        float2 sj1 = __ldg(&g_sj[d4.y]);
        float2 sj2 = __ldg(&g_sj[d4.z]);
        float2 sj3 = __ldg(&g_sj[d4.w]);
        float2 w0 = edge_w(si0, sj0);
        float2 w1 = edge_w(si1, sj1);
        float2 w2 = edge_w(si2, sj2);
        float2 w3 = edge_w(si3, sj3);
        asm volatile("red.global.add.v2.f32 [%0], {%1, %2};"
                     :: "l"(&g_c[d4.x]), "f"(w0.x), "f"(w0.y) : "memory");
        asm volatile("red.global.add.v2.f32 [%0], {%1, %2};"
                     :: "l"(&g_c[d4.y]), "f"(w1.x), "f"(w1.y) : "memory");
        asm volatile("red.global.add.v2.f32 [%0], {%1, %2};"
                     :: "l"(&g_c[d4.z]), "f"(w2.x), "f"(w2.y) : "memory");
        asm volatile("red.global.add.v2.f32 [%0], {%1, %2};"
                     :: "l"(&g_c[d4.w]), "f"(w3.x), "f"(w3.y) : "memory");
        z0 = w0.x + w1.x + w2.x + w3.x;
        z1 = w0.y + w1.y + w2.y + w3.y;
    } else {
        for (; k < E; k++) {
            int src = __ldg(ei + k);
            int dst = __ldg(ei + E + k);
            float2 w = edge_w(g_si[src], g_sj[dst]);
            asm volatile("red.global.add.v2.f32 [%0], {%1, %2};"
                         :: "l"(&g_c[dst]), "f"(w.x), "f"(w.y) : "memory");
            z0 += w.x;
            z1 += w.y;
        }
    }
#pragma unroll
    for (int off = 16; off; off >>= 1) {
        z0 += __shfl_xor_sync(0xffffffffu, z0, off);
        z1 += __shfl_xor_sync(0xffffffffu, z1, off);
    }
    __shared__ float s0[8], s1[8];
    int warp = threadIdx.x >> 5, lane = threadIdx.x & 31;
    if (lane == 0) { s0[warp] = z0; s1[warp] = z1; }
    __syncthreads();
    if (threadIdx.x == 0) {
        float t0 = 0.f, t1 = 0.f;
#pragma unroll
        for (int w = 0; w < 8; w++) { t0 += s0[w]; t1 += s1[w]; }
        asm volatile("red.global.add.v2.f32 [%0], {%1, %2};"
                     :: "l"(g_Z), "f"(t0), "f"(t1) : "memory");
    }
}

// ---------------------------------------------------------------------------
// 4) out = (x @ W) * c/Z -- tf32 mma.sync, persistent, B in registers (frozen)
#define XS_STRIDE 132
#define TILE_M    64

__device__ __forceinline__ void mma_tf32(float* d,
                                         unsigned a0, unsigned a1, unsigned a2, unsigned a3,
                                         unsigned b0, unsigned b1) {
    asm volatile("mma.sync.aligned.m16n8k8.row.col.f32.tf32.tf32.f32 "
                 "{%0,%1,%2,%3}, {%4,%5,%6,%7}, {%8,%9}, {%0,%1,%2,%3};"
                 : "+f"(d[0]), "+f"(d[1]), "+f"(d[2]), "+f"(d[3])
                 : "r"(a0), "r"(a1), "r"(a2), "r"(a3), "r"(b0), "r"(b1));
}

__global__ void __launch_bounds__(256, 2) out_gemm_kernel(const float* __restrict__ x,
                                                          float* __restrict__ out,
                                                          int N, int numTiles) {
    __shared__ unsigned xs[TILE_M * XS_STRIDE];   // f32-as-bits x tile

    int tid = threadIdx.x;
    int wn   = tid >> 5;            // warp 0..7 : 16-col band
    int lane = tid & 31;
    int g    = lane >> 2;
    int t    = lane & 3;
    int head = wn >> 2;
    float rz = 1.0f / g_Z[head];

    const float4* x4 = (const float4*)x;

    for (int tile = blockIdx.x; tile < numTiles; tile += gridDim.x) {
        int n0 = tile * TILE_M;
        __syncthreads();

#pragma unroll
        for (int it = 0; it < 8; it++) {
            int idx = tid + it * 256;
            int r   = idx >> 5;
            int k4  = idx & 31;
            int n   = n0 + r;
            float4 v = make_float4(0.f, 0.f, 0.f, 0.f);
            if (n < N) v = x4[(size_t)n * 32 + k4];
            *(uint4*)&xs[r * XS_STRIDE + k4 * 4] =
                make_uint4(__float_as_uint(v.x), __float_as_uint(v.y),
                           __float_as_uint(v.z), __float_as_uint(v.w));
        }
        __syncthreads();

        float acc[4][2][4];
#pragma unroll
        for (int mi = 0; mi < 4; mi++)
#pragma unroll
            for (int ni = 0; ni < 2; ni++)
#pragma unroll
                for (int q = 0; q < 4; q++) acc[mi][ni][q] = 0.f;

#pragma unroll
        for (int half = 0; half < 2; half++) {
            uint4 bh[8];
            const uint4* wp = (const uint4*)g_wpack + (wn * 16 + half * 8) * 32 + lane;
#pragma unroll
            for (int k2 = 0; k2 < 8; k2++) bh[k2] = wp[k2 * 32];

#pragma unroll
            for (int k2 = 0; k2 < 8; k2++) {
                int k0 = (half * 8 + k2) * 8;
                unsigned av[4][4];
#pragma unroll
                for (int mi = 0; mi < 4; mi++) {
                    int r0 = mi * 16;
                    av[mi][0] = f2tf32(__uint_as_float(xs[(r0 + g)     * XS_STRIDE + k0 + t]));
                    av[mi][1] = f2tf32(__uint_as_float(xs[(r0 + g + 8) * XS_STRIDE + k0 + t]));
                    av[mi][2] = f2tf32(__uint_as_float(xs[(r0 + g)     * XS_STRIDE + k0 + t + 4]));
                    av[mi][3] = f2tf32(__uint_as_float(xs[(r0 + g + 8) * XS_STRIDE + k0 + t + 4]));
                }
#pragma unroll
                for (int mi = 0; mi < 4; mi++) {
                    mma_tf32(acc[mi][0], av[mi][0], av[mi][1], av[mi][2], av[mi][3],
                             bh[k2].x, bh[k2].y);
                    mma_tf32(acc[mi][1], av[mi][0], av[mi][1], av[mi][2], av[mi][3],
                             bh[k2].z, bh[k2].w);
                }
            }
        }

#pragma unroll
        for (int mi = 0; mi < 4; mi++) {
            int r0 = n0 + mi * 16 + g;
            int r1 = r0 + 8;
            float scl0 = 0.f, scl1 = 0.f;
            if (r0 < N) {
                float2 cc = g_c[r0];
                scl0 = (head ? cc.y : cc.x) * rz;
            }
            if (r1 < N) {
                float2 cc = g_c[r1];
                scl1 = (head ? cc.y : cc.x) * rz;
            }
#pragma unroll
            for (int ni = 0; ni < 2; ni++) {
                int col = wn * 16 + ni * 8 + 2 * t;
                if (r0 < N)
                    *(float2*)&out[(size_t)r0 * 128 + col] =
                        make_float2(acc[mi][ni][0] * scl0, acc[mi][ni][1] * scl0);
                if (r1 < N)
                    *(float2*)&out[(size_t)r1 * 128 + col] =
                        make_float2(acc[mi][ni][2] * scl1, acc[mi][ni][3] * scl1);
            }
        }
    }
}

// ---------------------------------------------------------------------------
extern "C" void kernel_launch(void* const* d_in, const int* in_sizes, int n_in,
                              void* d_out, int out_size) {
    const float* x  = (const float*)d_in[0];
    const float* W  = (const float*)d_in[1];
    const float* a  = (const float*)d_in[2];
    const int*   ei = (const int*)d_in[3];
    float* out = (float*)d_out;

    int N = in_sizes[0] / IN_F;
    if (N > N_NODES) N = N_NODES;
    int E = in_sizes[3] / 2;
    int numTiles = (N + TILE_M - 1) / TILE_M;

    prep_kernel<<<64, 256>>>(W, a);
    node_s_kernel<<<(N + 7) / 8, 256>>>(x, N);
    edge_kernel<<<((E + 3) / 4 + 255) / 256, 256>>>(ei, E);

    int grid = numTiles < 296 ? numTiles : 296;
    out_gemm_kernel<<<grid, 256>>>(x, out, N, numTiles);
}

// round 16
// speedup vs baseline: 1.4002x; 1.0109x over previous
#include <cuda_runtime.h>

#define N_NODES 50000
#define IN_F    128
#define OUT_F   64
#define HEADS   2
#define ALPHA   0.2f

#define XS_STRIDE 132
#define TILE_M    64
#define NBLK      296     // 2 CTAs x 148 SMs, exact-fit residency

__device__ float  g_v[512];          // [which(i/j)][head][128]
__device__ float2 g_si[N_NODES];
__device__ float2 g_sj[N_NODES];
__device__ float2 g_c[N_NODES];      // per-node sum of exp(e) per head
__device__ float  g_Z[2];            // global softmax denominator per head
__device__ unsigned g_wpack[16384];  // W in tf32 MMA-fragment order (64KB)
__device__ unsigned g_barrier_ctr = 0;

__device__ __forceinline__ unsigned f2tf32(float f) {
    unsigned u;
    asm("cvt.rna.tf32.f32 %0, %1;" : "=r"(u) : "f"(f));
    return u;
}

// software grid barrier; monotonic counter -> safe across graph replays
__device__ __forceinline__ void grid_bar() {
    __syncthreads();
    if (threadIdx.x == 0) {
        unsigned old;
        asm volatile("atom.release.gpu.global.add.u32 %0, [%1], 1;"
                     : "=r"(old) : "l"(&g_barrier_ctr) : "memory");
        unsigned target = old - (old % NBLK) + NBLK;
        unsigned cur;
        do {
            asm volatile("ld.acquire.gpu.global.u32 %0, [%1];"
                         : "=r"(cur) : "l"(&g_barrier_ctr) : "memory");
        } while (cur < target);
    }
    __syncthreads();
}

__device__ __forceinline__ float2 edge_w(float2 si, float2 sj) {
    float e0 = si.x + sj.x;
    float e1 = si.y + sj.y;
    e0 = e0 > 0.f ? e0 : ALPHA * e0;
    e1 = e1 > 0.f ? e1 : ALPHA * e1;
    return make_float2(__expf(e0), __expf(e1));
}

__device__ __forceinline__ void mma_tf32(float* d,
                                         unsigned a0, unsigned a1, unsigned a2, unsigned a3,
                                         unsigned b0, unsigned b1) {
    asm volatile("mma.sync.aligned.m16n8k8.row.col.f32.tf32.tf32.f32 "
                 "{%0,%1,%2,%3}, {%4,%5,%6,%7}, {%8,%9}, {%0,%1,%2,%3};"
                 : "+f"(d[0]), "+f"(d[1]), "+f"(d[2]), "+f"(d[3])
                 : "r"(a0), "r"(a1), "r"(a2), "r"(a3), "r"(b0), "r"(b1));
}

// ---------------------------------------------------------------------------
// ONE persistent kernel: prep | barrier | node_s | barrier | edge | barrier | gemm
__global__ void __launch_bounds__(256, 2) gat_fused_kernel(
        const float* __restrict__ x, const float* __restrict__ W,
        const float* __restrict__ a, const int* __restrict__ ei,
        float* __restrict__ out, int N, int E, int numTiles) {
    __shared__ unsigned xs[TILE_M * XS_STRIDE];   // gemm A tile; aliased as vsm in node phase
    __shared__ float s0[8], s1[8];

    int tid = threadIdx.x;
    int bid = blockIdx.x;
    int warp = tid >> 5, lane = tid & 31;

    // ========== Phase A: prep (wpack + v + zero Z) ==========
    {
        int idx = bid * 256 + tid;
        if (idx < 16384) {
            int q    = idx & 3;
            int ln   = (idx >> 2) & 31;
            int ks   = (idx >> 7) & 15;
            int w    = (idx >> 11) & 7;
            int g = ln >> 2, t = ln & 3;
            int ni  = q >> 1;
            int sel = q & 1;
            int c = w * 16 + ni * 8 + g;          // output column (h*64+o)
            int k = ks * 8 + t + sel * 4;
            int h = c >> 6, o = c & 63;
            g_wpack[idx] = f2tf32(W[((size_t)h * 128 + k) * 64 + o]);
        }
        if (idx < 2) g_Z[idx] = 0.0f;
        if (idx < 512) {
            int which = idx >> 8;
            int h     = (idx >> 7) & 1;
            int i     = idx & 127;
            const float* wrow = W + h * (IN_F * OUT_F) + i * OUT_F;
            const float* av   = a + h * (2 * OUT_F) + which * OUT_F;
            float s = 0.f;
#pragma unroll 16
            for (int o = 0; o < OUT_F; o++) s += wrow[o] * av[o];
            g_v[which * 256 + h * 128 + i] = s;
        }
    }
    grid_bar();

    // ========== Phase B: per-node scores (warp per node, grid-stride) ==========
    {
        float* vsm = (float*)xs;
        vsm[tid]       = g_v[tid];
        vsm[tid + 256] = g_v[tid + 256];
        __syncthreads();

        const float4* v4 = (const float4*)vsm;
        float4 vi0 = v4[lane];
        float4 vi1 = v4[32 + lane];
        float4 vj0 = v4[64 + lane];
        float4 vj1 = v4[96 + lane];

        for (int n = bid * 8 + warp; n < N; n += NBLK * 8) {
            float4 xv = ((const float4*)x)[(size_t)n * 32 + lane];
            float si0 = xv.x*vi0.x + xv.y*vi0.y + xv.z*vi0.z + xv.w*vi0.w;
            float si1 = xv.x*vi1.x + xv.y*vi1.y + xv.z*vi1.z + xv.w*vi1.w;
            float sj0 = xv.x*vj0.x + xv.y*vj0.y + xv.z*vj0.z + xv.w*vj0.w;
            float sj1 = xv.x*vj1.x + xv.y*vj1.y + xv.z*vj1.z + xv.w*vj1.w;
#pragma unroll
            for (int off = 16; off; off >>= 1) {
                si0 += __shfl_xor_sync(0xffffffffu, si0, off);
                si1 += __shfl_xor_sync(0xffffffffu, si1, off);
                sj0 += __shfl_xor_sync(0xffffffffu, sj0, off);
                sj1 += __shfl_xor_sync(0xffffffffu, sj1, off);
            }
            if (lane == 0) {
                g_si[n] = make_float2(si0, si1);
                g_sj[n] = make_float2(sj0, sj1);
                g_c[n]  = make_float2(0.f, 0.f);
            }
        }
    }
    grid_bar();

    // ========== Phase C: edges (4 per thread, MLP-batched gathers) ==========
    {
        float z0 = 0.f, z1 = 0.f;
        int nQuads = (E + 3) >> 2;
        for (int k4 = bid * 256 + tid; k4 < nQuads; k4 += NBLK * 256) {
            int k = k4 * 4;
            if (k + 3 < E) {
                int4 s4 = *(const int4*)(ei + k);
                int4 d4 = *(const int4*)(ei + E + k);
                float2 si0 = __ldg(&g_si[s4.x]);
                float2 si1 = __ldg(&g_si[s4.y]);
                float2 si2 = __ldg(&g_si[s4.z]);
                float2 si3 = __ldg(&g_si[s4.w]);
                float2 sj0 = __ldg(&g_sj[d4.x]);
                float2 sj1 = __ldg(&g_sj[d4.y]);
                float2 sj2 = __ldg(&g_sj[d4.z]);
                float2 sj3 = __ldg(&g_sj[d4.w]);
                float2 w0 = edge_w(si0, sj0);
                float2 w1 = edge_w(si1, sj1);
                float2 w2 = edge_w(si2, sj2);
                float2 w3 = edge_w(si3, sj3);
                asm volatile("red.global.add.v2.f32 [%0], {%1, %2};"
                             :: "l"(&g_c[d4.x]), "f"(w0.x), "f"(w0.y) : "memory");
                asm volatile("red.global.add.v2.f32 [%0], {%1, %2};"
                             :: "l"(&g_c[d4.y]), "f"(w1.x), "f"(w1.y) : "memory");
                asm volatile("red.global.add.v2.f32 [%0], {%1, %2};"
                             :: "l"(&g_c[d4.z]), "f"(w2.x), "f"(w2.y) : "memory");
                asm volatile("red.global.add.v2.f32 [%0], {%1, %2};"
                             :: "l"(&g_c[d4.w]), "f"(w3.x), "f"(w3.y) : "memory");
                z0 += w0.x + w1.x + w2.x + w3.x;
                z1 += w0.y + w1.y + w2.y + w3.y;
            } else {
                for (; k < E; k++) {
                    int src = __ldg(ei + k);
                    int dst = __ldg(ei + E + k);
                    float2 w = edge_w(g_si[src], g_sj[dst]);
                    asm volatile("red.global.add.v2.f32 [%0], {%1, %2};"
                                 :: "l"(&g_c[dst]), "f"(w.x), "f"(w.y) : "memory");
                    z0 += w.x;
                    z1 += w.y;
                }
            }
        }
#pragma unroll
        for (int off = 16; off; off >>= 1) {
            z0 += __shfl_xor_sync(0xffffffffu, z0, off);
            z1 += __shfl_xor_sync(0xffffffffu, z1, off);
        }
        if (lane == 0) { s0[warp] = z0; s1[warp] = z1; }
        __syncthreads();
        if (tid == 0) {
            float t0 = 0.f, t1 = 0.f;
#pragma unroll
            for (int w = 0; w < 8; w++) { t0 += s0[w]; t1 += s1[w]; }
            asm volatile("red.global.add.v2.f32 [%0], {%1, %2};"
                         :: "l"(g_Z), "f"(t0), "f"(t1) : "memory");
        }
    }
    grid_bar();

    // ========== Phase D: gemm (tf32 mma.sync, B in registers, persistent) ==========
    {
        int wn   = warp;            // 16-col band
        int g    = lane >> 2;
        int t    = lane & 3;
        int head = wn >> 2;
        float rz = 1.0f / g_Z[head];
        const float4* x4 = (const float4*)x;

        for (int tile = bid; tile < numTiles; tile += NBLK) {
            int n0 = tile * TILE_M;
            __syncthreads();

            // stage x tile, tf32-converted AT STAGING (mainloop has zero CVTs)
#pragma unroll
            for (int it = 0; it < 8; it++) {
                int idx = tid + it * 256;
                int r   = idx >> 5;
                int k4  = idx & 31;
                int n   = n0 + r;
                float4 v = make_float4(0.f, 0.f, 0.f, 0.f);
                if (n < N) v = x4[(size_t)n * 32 + k4];
                *(uint4*)&xs[r * XS_STRIDE + k4 * 4] =
                    make_uint4(f2tf32(v.x), f2tf32(v.y), f2tf32(v.z), f2tf32(v.w));
            }
            __syncthreads();

            float acc[4][2][4];
#pragma unroll
            for (int mi = 0; mi < 4; mi++)
#pragma unroll
                for (int ni = 0; ni < 2; ni++)
#pragma unroll
                    for (int q = 0; q < 4; q++) acc[mi][ni][q] = 0.f;

#pragma unroll
            for (int half = 0; half < 2; half++) {
                uint4 bh[8];
                const uint4* wp = (const uint4*)g_wpack + (wn * 16 + half * 8) * 32 + lane;
#pragma unroll
                for (int k2 = 0; k2 < 8; k2++) bh[k2] = wp[k2 * 32];

#pragma unroll
                for (int k2 = 0; k2 < 8; k2++) {
                    int k0 = (half * 8 + k2) * 8;
                    unsigned av[4][4];
#pragma unroll
                    for (int mi = 0; mi < 4; mi++) {
                        int r0 = mi * 16;
                        av[mi][0] = xs[(r0 + g)     * XS_STRIDE + k0 + t];
                        av[mi][1] = xs[(r0 + g + 8) * XS_STRIDE + k0 + t];
                        av[mi][2] = xs[(r0 + g)     * XS_STRIDE + k0 + t + 4];
                        av[mi][3] = xs[(r0 + g + 8) * XS_STRIDE + k0 + t + 4];
                    }
#pragma unroll
                    for (int mi = 0; mi < 4; mi++) {
                        mma_tf32(acc[mi][0], av[mi][0], av[mi][1], av[mi][2], av[mi][3],
                                 bh[k2].x, bh[k2].y);
                        mma_tf32(acc[mi][1], av[mi][0], av[mi][1], av[mi][2], av[mi][3],
                                 bh[k2].z, bh[k2].w);
                    }
                }
            }

            // epilogue: scale by c[n,head]/Z_head
#pragma unroll
            for (int mi = 0; mi < 4; mi++) {
                int r0 = n0 + mi * 16 + g;
                int r1 = r0 + 8;
                float scl0 = 0.f, scl1 = 0.f;
                if (r0 < N) {
                    float2 cc = g_c[r0];
                    scl0 = (head ? cc.y : cc.x) * rz;
                }
                if (r1 < N) {
                    float2 cc = g_c[r1];
                    scl1 = (head ? cc.y : cc.x) * rz;
                }
#pragma unroll
                for (int ni = 0; ni < 2; ni++) {
                    int col = wn * 16 + ni * 8 + 2 * t;
                    if (r0 < N)
                        *(float2*)&out[(size_t)r0 * 128 + col] =
                            make_float2(acc[mi][ni][0] * scl0, acc[mi][ni][1] * scl0);
                    if (r1 < N)
                        *(float2*)&out[(size_t)r1 * 128 + col] =
                            make_float2(acc[mi][ni][2] * scl1, acc[mi][ni][3] * scl1);
                }
            }
        }
    }
}

// ---------------------------------------------------------------------------
extern "C" void kernel_launch(void* const* d_in, const int* in_sizes, int n_in,
                              void* d_out, int out_size) {
    const float* x  = (const float*)d_in[0];
    const float* W  = (const float*)d_in[1];
    const float* a  = (const float*)d_in[2];
    const int*   ei = (const int*)d_in[3];
    float* out = (float*)d_out;

    int N = in_sizes[0] / IN_F;
    if (N > N_NODES) N = N_NODES;
    int E = in_sizes[3] / 2;
    int numTiles = (N + TILE_M - 1) / TILE_M;

    gat_fused_kernel<<<NBLK, 256>>>(x, W, a, ei, out, N, E, numTiles);
}